// round 16
// baseline (speedup 1.0000x reference)
#include <cuda_runtime.h>
#include <cuda_fp16.h>
#include <cstdint>

// Z[b,w,t] = sum_c Q[b,w,c] * ( K[b,w+t,c] + bias[c,t] ),  B=16, T=1024, C=128.
//
// Pre-pass: Q,K -> fp16 globals; bias -> fp16 transposed g_b16[t][c]. (MLP-2 convert)
// Main kernel (warp-specialized, all m=32 tiles):
//   warps 0-7  = band GEMM  (4 m-tiles x 2 col-halves, 160-col window)
//   warps 8-15 = bias GEMM  (4 m-tiles x 2 col-halves, 128 bias cols)   CONCURRENT
// Band warps bar.sync(1) then scatter to smem zs (overlay on panel); full sync;
// bias warps run the fused epilogue (Z = zs + PB).

#define TDIM   1024
#define CDIM   128
#define KROWS  2047
#define NTHREADS 512

#define NQ   (16 * 1024 * 128)          // 2097152
#define NK   (16 * 2047 * 128)          // 4192256
#define NB   (1024 * 128)               // 131072

static __device__ __half g_q16[NQ];     // [b][w][c]
static __device__ __half g_k16[NK];     // [b][u][c]
static __device__ __half g_b16[NB];     // [t][c]  (transposed bias)

// ---- smem layout (bytes); fp16 buffers: rows of 256B, 16B chunks XOR-swizzled ----
#define OQ  0                            // Q fp16 (128 x 256B) = 32768
#define OPH 32768                        // K panel (256 x 256B) = 65536
#define OZS OPH                          // fp32 Z overlay (128 x 132 x 4 = 67584)
#define ZSTRIDE 132
#define OBH (OPH + 67584)                // bias B (128 x 256B) at 100352
#define SMEM_BYTES (OBH + 32768)         // 133120

__device__ __forceinline__ void ldsm4(uint32_t addr, uint32_t& r0, uint32_t& r1,
                                      uint32_t& r2, uint32_t& r3) {
    asm volatile("ldmatrix.sync.aligned.m8n8.x4.shared.b16 {%0,%1,%2,%3}, [%4];"
                 : "=r"(r0), "=r"(r1), "=r"(r2), "=r"(r3) : "r"(addr));
}
__device__ __forceinline__ void mma16816(float* d, uint32_t a0, uint32_t a1,
                                         uint32_t a2, uint32_t a3,
                                         uint32_t b0, uint32_t b1) {
    asm volatile("mma.sync.aligned.m16n8k16.row.col.f32.f16.f16.f32 "
                 "{%0,%1,%2,%3}, {%4,%5,%6,%7}, {%8,%9}, {%0,%1,%2,%3};"
                 : "+f"(d[0]), "+f"(d[1]), "+f"(d[2]), "+f"(d[3])
                 : "r"(a0), "r"(a1), "r"(a2), "r"(a3), "r"(b0), "r"(b1));
}
__device__ __forceinline__ uint32_t smem_u32(const void* p) {
    uint32_t a;
    asm("{ .reg .u64 t; cvta.to.shared.u64 t, %1; cvt.u32.u64 %0, t; }" : "=r"(a) : "l"(p));
    return a;
}
__device__ __forceinline__ uint32_t pack_h2(float x, float y) {
    __half2 h = __halves2half2(__float2half_rn(x), __float2half_rn(y));
    return *reinterpret_cast<uint32_t*>(&h);
}

// ===================== pre-pass: Q,K convert (MLP 2) + bias transpose =====================
#define QK_BLOCKS 3071                   // 3071*256 threads x 2 float4 = (NQ+NK)/4 exactly
__global__ void cvt_all_kernel(const float* __restrict__ Q,
                               const float* __restrict__ K,
                               const float* __restrict__ bias)
{
    if (blockIdx.x < QK_BLOCKS) {
        const int half = QK_BLOCKS * 256;                // 786176
        int i0 = blockIdx.x * 256 + threadIdx.x;
#pragma unroll
        for (int p = 0; p < 2; p++) {
            int i = i0 + p * half;
            if (i < NQ / 4) {
                float4 v = *reinterpret_cast<const float4*>(Q + 4 * (size_t)i);
                *reinterpret_cast<uint2*>(g_q16 + 4 * (size_t)i) =
                    make_uint2(pack_h2(v.x, v.y), pack_h2(v.z, v.w));
            } else {
                size_t j = (size_t)(i - NQ / 4);
                float4 v = *reinterpret_cast<const float4*>(K + 4 * j);
                *reinterpret_cast<uint2*>(g_k16 + 4 * j) =
                    make_uint2(pack_h2(v.x, v.y), pack_h2(v.z, v.w));
            }
        }
    } else {
        // bias[c][t] (128 x 1024 f32) -> g_b16[t][c]; 128 blocks of 32x32 tiles
        __shared__ float s[32][33];
        const int bb = blockIdx.x - QK_BLOCKS;           // 0..127
        const int t0 = (bb & 31) * 32;
        const int c0 = (bb >> 5) * 32;
        const int tx = threadIdx.x & 31;
        const int ty = threadIdx.x >> 5;                 // 0..7
#pragma unroll
        for (int r = 0; r < 4; r++) {
            int cc = ty + 8 * r;
            s[cc][tx] = bias[(size_t)(c0 + cc) * TDIM + t0 + tx];
        }
        __syncthreads();
#pragma unroll
        for (int r = 0; r < 4; r++) {
            int tt = ty + 8 * r;
            g_b16[(size_t)(t0 + tt) * CDIM + c0 + tx] = __float2half_rn(s[tx][tt]);
        }
    }
}

// ===================== main kernel =====================
__global__ __launch_bounds__(NTHREADS, 1)
void sw_fused_kernel(float* __restrict__ Z)
{
    extern __shared__ char smem[];
    const uint32_t sb = smem_u32(smem);
    float* zs = reinterpret_cast<float*>(smem + OZS);

    const int tid  = threadIdx.x;
    const int wid  = tid >> 5;
    const int lane = tid & 31;

    const int b  = blockIdx.z;
    const int w0 = blockIdx.y * 128;
    const int t0 = blockIdx.x * 128;
    const int u0 = w0 + t0;

    float* Zb = Z + ((size_t)b * TDIM + w0) * TDIM + t0;

    const uint32_t rx  = lane & 7;
    const uint32_t aC2 = lane >> 4;
    const uint32_t bC2 = (lane >> 3) & 1;
    const int er = lane >> 2;
    const int ec = (lane & 3) * 2;

    // ---- stage Q: 2048 x 16B chunks ----
#pragma unroll
    for (int r = 0; r < 4; r++) {
        int idx = tid + NTHREADS * r;
        int row = idx >> 4, c2 = idx & 15;
        uint4 v = *reinterpret_cast<const uint4*>(
            g_q16 + ((size_t)(b * TDIM + w0 + row)) * CDIM + c2 * 8);
        *reinterpret_cast<uint4*>(smem + OQ + row * 256 + ((c2 ^ (row & 7)) << 4)) = v;
    }
    // ---- stage K panel: 256 rows x 16 chunks = 4096 (exact) ----
#pragma unroll
    for (int r = 0; r < 8; r++) {
        int idx = tid + NTHREADS * r;
        int row = idx >> 4, c2 = idx & 15;
        int u = u0 + row;
        if (u > 2046) u = 2046;                  // only last row of last tile; discarded taus
        uint4 v = *reinterpret_cast<const uint4*>(
            g_k16 + ((size_t)(b * KROWS + u)) * CDIM + c2 * 8);
        *reinterpret_cast<uint4*>(smem + OPH + row * 256 + ((c2 ^ (row & 7)) << 4)) = v;
    }
    // ---- stage bias: 2048 x 16B chunks (already transposed) ----
#pragma unroll
    for (int r = 0; r < 4; r++) {
        int idx = tid + NTHREADS * r;
        int row = idx >> 4, c2 = idx & 15;       // row = tau
        uint4 v = *reinterpret_cast<const uint4*>(
            g_b16 + ((size_t)(t0 + row)) * CDIM + c2 * 8);
        *reinterpret_cast<uint4*>(smem + OBH + row * 256 + ((c2 ^ (row & 7)) << 4)) = v;
    }
    __syncthreads();

    if (wid < 8) {
        // ===================== band GEMM: warps 0-7, m=32 tiles =====================
        const int mt = wid >> 1;                 // 0..3, rows [32mt, 32mt+32)
        const int h  = wid & 1;                  // cols [80h, 80h+80)
        const int im = mt * 32;
        uint32_t aRowB[2];
#pragma unroll
        for (int mf = 0; mf < 2; mf++)
            aRowB[mf] = (uint32_t)((im + 16 * mf + (lane & 15)) * 256);
        uint32_t bRowG[5];
#pragma unroll
        for (int g = 0; g < 5; g++)
            bRowG[g] = (uint32_t)((im + 80 * h + 16 * g + ((lane >> 4) << 3) + (lane & 7)) * 256);

        float acc[2][10][4];                     // [mfrag][nfrag][elem]
#pragma unroll
        for (int m = 0; m < 2; m++)
#pragma unroll
            for (int n = 0; n < 10; n++)
#pragma unroll
                for (int e = 0; e < 4; e++) acc[m][n][e] = 0.f;

#pragma unroll
        for (int st = 0; st < 8; st++) {
            uint32_t kc = 2u * (uint32_t)st;
            uint32_t aoff = ((kc + aC2) ^ rx) << 4;
            uint32_t boff = ((kc + bC2) ^ rx) << 4;
            uint32_t a0,a1,a2,a3,a4,a5,a6,a7;
            ldsm4(sb + OQ + aRowB[0] + aoff, a0,a1,a2,a3);
            ldsm4(sb + OQ + aRowB[1] + aoff, a4,a5,a6,a7);
#pragma unroll
            for (int g = 0; g < 5; g++) {
                uint32_t b0,b1,b2,b3;
                ldsm4(sb + OPH + bRowG[g] + boff, b0,b1,b2,b3);
                mma16816(acc[0][2*g    ], a0,a1,a2,a3, b0,b1);
                mma16816(acc[0][2*g + 1], a0,a1,a2,a3, b2,b3);
                mma16816(acc[1][2*g    ], a4,a5,a6,a7, b0,b1);
                mma16816(acc[1][2*g + 1], a4,a5,a6,a7, b2,b3);
            }
        }
        // band warps only: all panel reads done before zs overlay is written
        asm volatile("bar.sync 1, 256;" ::: "memory");

        // ---- scatter (pure assignment): zs[im+r, j-r] = D[r, j] ----
#pragma unroll
        for (int mf = 0; mf < 2; mf++)
#pragma unroll
            for (int nf = 0; nf < 10; nf++)
#pragma unroll
                for (int e = 0; e < 4; e++) {
                    int r = 16 * mf + er + ((e & 2) ? 8 : 0);
                    int j = 80 * h + nf * 8 + ec + (e & 1);
                    int tau = j - r;
                    if ((unsigned)tau < 128u)
                        zs[(im + r) * ZSTRIDE + tau] = acc[mf][nf][e];
                }
        __syncthreads();
    } else {
        // ===================== bias GEMM: warps 8-15, m=32 x n=64 tiles =====================
        const int wq  = wid - 8;                 // 0..7
        const int mt2 = wq >> 1;                 // 0..3, rows [32mt2, 32mt2+32)
        const int hc  = wq & 1;                  // cols [64hc, 64hc+64)
        const int im2 = mt2 * 32;
        uint32_t aRowB2[2];
#pragma unroll
        for (int mf = 0; mf < 2; mf++)
            aRowB2[mf] = (uint32_t)((im2 + 16 * mf + (lane & 15)) * 256);
        uint32_t bRow[4];
#pragma unroll
        for (int p = 0; p < 4; p++)
            bRow[p] = (uint32_t)((64 * hc + 16 * p + ((lane >> 4) << 3) + (lane & 7)) * 256);

        float acc[2][8][4];                      // [mfrag][nfrag][elem]
#pragma unroll
        for (int m = 0; m < 2; m++)
#pragma unroll
            for (int n = 0; n < 8; n++)
#pragma unroll
                for (int e = 0; e < 4; e++) acc[m][n][e] = 0.f;

#pragma unroll
        for (int st = 0; st < 8; st++) {
            uint32_t kc = 2u * (uint32_t)st;
            uint32_t aoff = ((kc + aC2) ^ rx) << 4;
            uint32_t boff = ((kc + bC2) ^ rx) << 4;
            uint32_t a0,a1,a2,a3,a4,a5,a6,a7;
            ldsm4(sb + OQ + aRowB2[0] + aoff, a0,a1,a2,a3);
            ldsm4(sb + OQ + aRowB2[1] + aoff, a4,a5,a6,a7);
#pragma unroll
            for (int p = 0; p < 4; p++) {
                uint32_t b0,b1,b2,b3;
                ldsm4(sb + OBH + bRow[p] + boff, b0,b1,b2,b3);
                mma16816(acc[0][2*p    ], a0,a1,a2,a3, b0,b1);
                mma16816(acc[0][2*p + 1], a0,a1,a2,a3, b2,b3);
                mma16816(acc[1][2*p    ], a4,a5,a6,a7, b0,b1);
                mma16816(acc[1][2*p + 1], a4,a5,a6,a7, b2,b3);
            }
        }
        __syncthreads();   // wait for band scatter to land in zs

        // ---- fused epilogue: Z = zs + PB, direct STG ----
#pragma unroll
        for (int mf = 0; mf < 2; mf++) {
            const int i0 = im2 + 16 * mf + er;
#pragma unroll
            for (int nf = 0; nf < 8; nf++) {
                int tau = 64 * hc + nf * 8 + ec;
                const float* z0 = zs + i0 * ZSTRIDE + tau;
                const float* z1 = zs + (i0 + 8) * ZSTRIDE + tau;
                *reinterpret_cast<float2*>(Zb + (size_t)i0 * TDIM + tau) =
                    make_float2(acc[mf][nf][0] + z0[0], acc[mf][nf][1] + z0[1]);
                *reinterpret_cast<float2*>(Zb + (size_t)(i0 + 8) * TDIM + tau) =
                    make_float2(acc[mf][nf][2] + z1[0], acc[mf][nf][3] + z1[1]);
            }
        }
    }
}

extern "C" void kernel_launch(void* const* d_in, const int* in_sizes, int n_in,
                              void* d_out, int out_size)
{
    const float* Q    = (const float*)d_in[0];   // (16, 1024, 128)
    const float* Km   = (const float*)d_in[1];   // (16, 2047, 128)
    const float* bias = (const float*)d_in[2];   // (1, 1, 128, 1024)
    float* Z          = (float*)d_out;           // (16, 1024, 1024)

    cudaFuncSetAttribute(sw_fused_kernel, cudaFuncAttributeMaxDynamicSharedMemorySize, SMEM_BYTES);

    cvt_all_kernel<<<QK_BLOCKS + 128, 256>>>(Q, Km, bias);

    dim3 grid(TDIM / 128, TDIM / 128, 16);       // (8, 8, 16) = 1024 CTAs
    sw_fused_kernel<<<grid, NTHREADS, SMEM_BYTES>>>(Z);
}

// round 17
// speedup vs baseline: 1.1245x; 1.1245x over previous
#include <cuda_runtime.h>
#include <cuda_fp16.h>
#include <cstdint>

// Z[b,w,t] = sum_c Q[b,w,c] * ( K[b,w+t,c] + bias[c,t] ),  B=16, T=1024, C=128.
//
// Pre-pass: Q,K -> fp16 globals; bias -> fp16 transposed g_b16[t][c].
// Main kernel (warp-specialized, cp.async staging, named-barrier dataflow):
//   warps 0-7  (band): cp.async K panel -> bar3 -> band GEMM -> bar1 -> scatter -> arrive bar4
//   warps 8-15 (bias): cp.async Q -> arrive bar3; cp.async bias -> bar2 -> bias GEMM
//                      -> bar4 -> fused epilogue (Z = zs + PB)

#define TDIM   1024
#define CDIM   128
#define KROWS  2047
#define NTHREADS 512

#define NQ   (16 * 1024 * 128)
#define NK   (16 * 2047 * 128)
#define NB   (1024 * 128)

static __device__ __half g_q16[NQ];     // [b][w][c]
static __device__ __half g_k16[NK];     // [b][u][c]
static __device__ __half g_b16[NB];     // [t][c]  (transposed bias)

// ---- smem layout (bytes); fp16 buffers: rows of 256B, 16B chunks XOR-swizzled ----
#define OQ  0                            // Q fp16 (128 x 256B) = 32768
#define OPH 32768                        // K panel (256 x 256B) = 65536
#define OZS OPH                          // fp32 Z overlay (128 x 132 x 4 = 67584)
#define ZSTRIDE 132
#define OBH (OPH + 67584)                // bias B (128 x 256B) at 100352
#define SMEM_BYTES (OBH + 32768)         // 133120

#define CP_ASYNC16(dst, src) \
    asm volatile("cp.async.cg.shared.global [%0], [%1], 16;" \
                 :: "r"(dst), "l"(src) : "memory")
#define CP_COMMIT()  asm volatile("cp.async.commit_group;" ::: "memory")
#define CP_WAIT(N)   asm volatile("cp.async.wait_group %0;" :: "n"(N) : "memory")

__device__ __forceinline__ void ldsm4(uint32_t addr, uint32_t& r0, uint32_t& r1,
                                      uint32_t& r2, uint32_t& r3) {
    asm volatile("ldmatrix.sync.aligned.m8n8.x4.shared.b16 {%0,%1,%2,%3}, [%4];"
                 : "=r"(r0), "=r"(r1), "=r"(r2), "=r"(r3) : "r"(addr));
}
__device__ __forceinline__ void mma16816(float* d, uint32_t a0, uint32_t a1,
                                         uint32_t a2, uint32_t a3,
                                         uint32_t b0, uint32_t b1) {
    asm volatile("mma.sync.aligned.m16n8k16.row.col.f32.f16.f16.f32 "
                 "{%0,%1,%2,%3}, {%4,%5,%6,%7}, {%8,%9}, {%0,%1,%2,%3};"
                 : "+f"(d[0]), "+f"(d[1]), "+f"(d[2]), "+f"(d[3])
                 : "r"(a0), "r"(a1), "r"(a2), "r"(a3), "r"(b0), "r"(b1));
}
__device__ __forceinline__ uint32_t smem_u32(const void* p) {
    uint32_t a;
    asm("{ .reg .u64 t; cvta.to.shared.u64 t, %1; cvt.u32.u64 %0, t; }" : "=r"(a) : "l"(p));
    return a;
}
__device__ __forceinline__ uint32_t pack_h2(float x, float y) {
    __half2 h = __halves2half2(__float2half_rn(x), __float2half_rn(y));
    return *reinterpret_cast<uint32_t*>(&h);
}

// ===================== pre-pass: Q,K convert (MLP 2) + bias transpose =====================
#define QK_BLOCKS 3071                   // 3071*256 threads x 2 float4 = (NQ+NK)/4 exactly
__global__ void cvt_all_kernel(const float* __restrict__ Q,
                               const float* __restrict__ K,
                               const float* __restrict__ bias)
{
    if (blockIdx.x < QK_BLOCKS) {
        const int half = QK_BLOCKS * 256;                // 786176
        int i0 = blockIdx.x * 256 + threadIdx.x;
#pragma unroll
        for (int p = 0; p < 2; p++) {
            int i = i0 + p * half;
            if (i < NQ / 4) {
                float4 v = *reinterpret_cast<const float4*>(Q + 4 * (size_t)i);
                *reinterpret_cast<uint2*>(g_q16 + 4 * (size_t)i) =
                    make_uint2(pack_h2(v.x, v.y), pack_h2(v.z, v.w));
            } else {
                size_t j = (size_t)(i - NQ / 4);
                float4 v = *reinterpret_cast<const float4*>(K + 4 * j);
                *reinterpret_cast<uint2*>(g_k16 + 4 * j) =
                    make_uint2(pack_h2(v.x, v.y), pack_h2(v.z, v.w));
            }
        }
    } else {
        // bias[c][t] (128 x 1024 f32) -> g_b16[t][c]; 128 blocks of 32x32 tiles
        __shared__ float s[32][33];
        const int bb = blockIdx.x - QK_BLOCKS;           // 0..127
        const int t0 = (bb & 31) * 32;
        const int c0 = (bb >> 5) * 32;
        const int tx = threadIdx.x & 31;
        const int ty = threadIdx.x >> 5;                 // 0..7
#pragma unroll
        for (int r = 0; r < 4; r++) {
            int cc = ty + 8 * r;
            s[cc][tx] = bias[(size_t)(c0 + cc) * TDIM + t0 + tx];
        }
        __syncthreads();
#pragma unroll
        for (int r = 0; r < 4; r++) {
            int tt = ty + 8 * r;
            g_b16[(size_t)(t0 + tt) * CDIM + c0 + tx] = __float2half_rn(s[tx][tt]);
        }
    }
}

// ===================== main kernel =====================
__global__ __launch_bounds__(NTHREADS, 1)
void sw_fused_kernel(float* __restrict__ Z)
{
    extern __shared__ char smem[];
    const uint32_t sb = smem_u32(smem);
    float* zs = reinterpret_cast<float*>(smem + OZS);

    const int tid  = threadIdx.x;
    const int wid  = tid >> 5;
    const int lane = tid & 31;

    const int b  = blockIdx.z;
    const int w0 = blockIdx.y * 128;
    const int t0 = blockIdx.x * 128;
    const int u0 = w0 + t0;

    float* Zb = Z + ((size_t)b * TDIM + w0) * TDIM + t0;

    const uint32_t rx  = lane & 7;
    const uint32_t aC2 = lane >> 4;
    const uint32_t bC2 = (lane >> 3) & 1;
    const int er = lane >> 2;
    const int ec = (lane & 3) * 2;

    if (wid < 8) {
        // =========== band group: stage K panel (256 rows x 16 chunks) ===========
#pragma unroll
        for (int r = 0; r < 16; r++) {
            int idx = tid + 256 * r;             // 0..4095
            int row = idx >> 4, c2 = idx & 15;
            int u = u0 + row;
            if (u > 2046) u = 2046;              // clamped rows feed discarded taus only
            const __half* src = g_k16 + ((size_t)(b * KROWS + u)) * CDIM + c2 * 8;
            CP_ASYNC16(sb + OPH + row * 256 + ((c2 ^ (row & 7)) << 4), src);
        }
        CP_COMMIT();
        CP_WAIT(0);
        asm volatile("bar.sync 3, 512;" ::: "memory");   // + Q staged (bias group arrived)

        // ===================== band GEMM: m=32 tiles =====================
        const int mt = wid >> 1;                 // 0..3, rows [32mt, 32mt+32)
        const int h  = wid & 1;                  // cols [80h, 80h+80)
        const int im = mt * 32;
        uint32_t aRowB[2];
#pragma unroll
        for (int mf = 0; mf < 2; mf++)
            aRowB[mf] = (uint32_t)((im + 16 * mf + (lane & 15)) * 256);
        uint32_t bRowG[5];
#pragma unroll
        for (int g = 0; g < 5; g++)
            bRowG[g] = (uint32_t)((im + 80 * h + 16 * g + ((lane >> 4) << 3) + (lane & 7)) * 256);

        float acc[2][10][4];
#pragma unroll
        for (int m = 0; m < 2; m++)
#pragma unroll
            for (int n = 0; n < 10; n++)
#pragma unroll
                for (int e = 0; e < 4; e++) acc[m][n][e] = 0.f;

#pragma unroll
        for (int st = 0; st < 8; st++) {
            uint32_t kc = 2u * (uint32_t)st;
            uint32_t aoff = ((kc + aC2) ^ rx) << 4;
            uint32_t boff = ((kc + bC2) ^ rx) << 4;
            uint32_t a0,a1,a2,a3,a4,a5,a6,a7;
            ldsm4(sb + OQ + aRowB[0] + aoff, a0,a1,a2,a3);
            ldsm4(sb + OQ + aRowB[1] + aoff, a4,a5,a6,a7);
#pragma unroll
            for (int g = 0; g < 5; g++) {
                uint32_t b0,b1,b2,b3;
                ldsm4(sb + OPH + bRowG[g] + boff, b0,b1,b2,b3);
                mma16816(acc[0][2*g    ], a0,a1,a2,a3, b0,b1);
                mma16816(acc[0][2*g + 1], a0,a1,a2,a3, b2,b3);
                mma16816(acc[1][2*g    ], a4,a5,a6,a7, b0,b1);
                mma16816(acc[1][2*g + 1], a4,a5,a6,a7, b2,b3);
            }
        }
        // band group only: all panel reads done before zs overlay is written
        asm volatile("bar.sync 1, 256;" ::: "memory");

        // ---- scatter (pure assignment): zs[im+r, j-r] = D[r, j] ----
#pragma unroll
        for (int mf = 0; mf < 2; mf++)
#pragma unroll
            for (int nf = 0; nf < 10; nf++)
#pragma unroll
                for (int e = 0; e < 4; e++) {
                    int r = 16 * mf + er + ((e & 2) ? 8 : 0);
                    int j = 80 * h + nf * 8 + ec + (e & 1);
                    int tau = j - r;
                    if ((unsigned)tau < 128u)
                        zs[(im + r) * ZSTRIDE + tau] = acc[mf][nf][e];
                }
        asm volatile("bar.arrive 4, 512;" ::: "memory");
    } else {
        // =========== bias group: stage Q then bias ===========
        const int t2 = tid - 256;                // 0..255
#pragma unroll
        for (int r = 0; r < 8; r++) {
            int idx = t2 + 256 * r;              // 0..2047
            int row = idx >> 4, c2 = idx & 15;
            const __half* src = g_q16 + ((size_t)(b * TDIM + w0 + row)) * CDIM + c2 * 8;
            CP_ASYNC16(sb + OQ + row * 256 + ((c2 ^ (row & 7)) << 4), src);
        }
        CP_COMMIT();                             // group: Q
#pragma unroll
        for (int r = 0; r < 8; r++) {
            int idx = t2 + 256 * r;              // 0..2047
            int row = idx >> 4, c2 = idx & 15;   // row = tau
            const __half* src = g_b16 + ((size_t)(t0 + row)) * CDIM + c2 * 8;
            CP_ASYNC16(sb + OBH + row * 256 + ((c2 ^ (row & 7)) << 4), src);
        }
        CP_COMMIT();                             // group: bias
        CP_WAIT(1);                              // Q complete
        asm volatile("bar.arrive 3, 512;" ::: "memory");
        CP_WAIT(0);                              // bias complete
        asm volatile("bar.sync 2, 256;" ::: "memory");   // bias group: Q+bias visible

        // ===================== bias GEMM: m=32 x n=64 tiles =====================
        const int wq  = wid - 8;                 // 0..7
        const int mt2 = wq >> 1;                 // 0..3, rows [32mt2, 32mt2+32)
        const int hc  = wq & 1;                  // cols [64hc, 64hc+64)
        const int im2 = mt2 * 32;
        uint32_t aRowB2[2];
#pragma unroll
        for (int mf = 0; mf < 2; mf++)
            aRowB2[mf] = (uint32_t)((im2 + 16 * mf + (lane & 15)) * 256);
        uint32_t bRow[4];
#pragma unroll
        for (int p = 0; p < 4; p++)
            bRow[p] = (uint32_t)((64 * hc + 16 * p + ((lane >> 4) << 3) + (lane & 7)) * 256);

        float acc[2][8][4];
#pragma unroll
        for (int m = 0; m < 2; m++)
#pragma unroll
            for (int n = 0; n < 8; n++)
#pragma unroll
                for (int e = 0; e < 4; e++) acc[m][n][e] = 0.f;

#pragma unroll
        for (int st = 0; st < 8; st++) {
            uint32_t kc = 2u * (uint32_t)st;
            uint32_t aoff = ((kc + aC2) ^ rx) << 4;
            uint32_t boff = ((kc + bC2) ^ rx) << 4;
            uint32_t a0,a1,a2,a3,a4,a5,a6,a7;
            ldsm4(sb + OQ + aRowB2[0] + aoff, a0,a1,a2,a3);
            ldsm4(sb + OQ + aRowB2[1] + aoff, a4,a5,a6,a7);
#pragma unroll
            for (int p = 0; p < 4; p++) {
                uint32_t b0,b1,b2,b3;
                ldsm4(sb + OBH + bRow[p] + boff, b0,b1,b2,b3);
                mma16816(acc[0][2*p    ], a0,a1,a2,a3, b0,b1);
                mma16816(acc[0][2*p + 1], a0,a1,a2,a3, b2,b3);
                mma16816(acc[1][2*p    ], a4,a5,a6,a7, b0,b1);
                mma16816(acc[1][2*p + 1], a4,a5,a6,a7, b2,b3);
            }
        }
        asm volatile("bar.sync 4, 512;" ::: "memory");   // wait for band scatter in zs

        // ---- fused epilogue: Z = zs + PB, direct STG ----
#pragma unroll
        for (int mf = 0; mf < 2; mf++) {
            const int i0 = im2 + 16 * mf + er;
#pragma unroll
            for (int nf = 0; nf < 8; nf++) {
                int tau = 64 * hc + nf * 8 + ec;
                const float* z0 = zs + i0 * ZSTRIDE + tau;
                const float* z1 = zs + (i0 + 8) * ZSTRIDE + tau;
                *reinterpret_cast<float2*>(Zb + (size_t)i0 * TDIM + tau) =
                    make_float2(acc[mf][nf][0] + z0[0], acc[mf][nf][1] + z0[1]);
                *reinterpret_cast<float2*>(Zb + (size_t)(i0 + 8) * TDIM + tau) =
                    make_float2(acc[mf][nf][2] + z1[0], acc[mf][nf][3] + z1[1]);
            }
        }
    }
}

extern "C" void kernel_launch(void* const* d_in, const int* in_sizes, int n_in,
                              void* d_out, int out_size)
{
    const float* Q    = (const float*)d_in[0];   // (16, 1024, 128)
    const float* Km   = (const float*)d_in[1];   // (16, 2047, 128)
    const float* bias = (const float*)d_in[2];   // (1, 1, 128, 1024)
    float* Z          = (float*)d_out;           // (16, 1024, 1024)

    cudaFuncSetAttribute(sw_fused_kernel, cudaFuncAttributeMaxDynamicSharedMemorySize, SMEM_BYTES);

    cvt_all_kernel<<<QK_BLOCKS + 128, 256>>>(Q, Km, bias);

    dim3 grid(TDIM / 128, TDIM / 128, 16);       // (8, 8, 16) = 1024 CTAs
    sw_fused_kernel<<<grid, NTHREADS, SMEM_BYTES>>>(Z);
}